// round 15
// baseline (speedup 1.0000x reference)
#include <cuda_runtime.h>
#include <math.h>

#define EDIM   256
#define HDIM   512
#define BATCH  32
#define SEQ    512
#define G3     1536
#define NCTA   128
#define DPC    4
#define GRUT   512

// ---- f32x2 packed helpers (sm_103a FFMA2; full fp32 precision) ----
__device__ __forceinline__ void fma2(unsigned long long& a,
                                     unsigned long long x, unsigned long long y) {
    asm("fma.rn.f32x2 %0, %1, %2, %0;" : "+l"(a) : "l"(x), "l"(y));
}
__device__ __forceinline__ unsigned long long pk(float lo, float hi) {
    unsigned long long r;
    asm("mov.b64 %0, {%1, %2};" : "=l"(r) : "f"(lo), "f"(hi));
    return r;
}
__device__ __forceinline__ float2 upk(unsigned long long v) {
    float2 r; asm("mov.b64 {%0, %1}, %2;" : "=f"(r.x), "=f"(r.y) : "l"(v));
    return r;
}
__device__ __forceinline__ float ldcg(const float* p) {
    float v; asm volatile("ld.global.cg.f32 %0, [%1];" : "=f"(v) : "l"(p));
    return v;
}
__device__ __forceinline__ void stcg(float* p, float v) {
    asm volatile("st.global.cg.f32 [%0], %1;" :: "l"(p), "f"(v));
}

// ---- scratch (device globals; no allocations allowed) ----
__device__ float d_induced[EDIM];
__device__ float d_e2[SEQ * BATCH * EDIM];            // [t][b][k]
__device__ float d_xi[(size_t)SEQ * G3 * BATCH];      // [t][g][b]
__device__ float d_h2[2 * HDIM * BATCH];              // [buf][d][b]
__device__ float d_pooled[BATCH * HDIM];              // [b][d]
__device__ unsigned d_leaf[8 * 32];                   // 8 leaf counters, 128B apart
__device__ unsigned d_root;                           // root arrival counter
__device__ unsigned d_gen;                            // released generation

// ---- init: induced = induction @ unk, h0 = 0, barrier reset ----
__global__ void init_kernel(const float* __restrict__ induction,
                            const float* __restrict__ unk) {
    int i = threadIdx.x;                               // 256 threads
    if (i < 8 * 32) d_leaf[i] = 0u;
    if (i == 0) { d_root = 0u; d_gen = 0u; }
    const float* row = induction + (size_t)i * EDIM;
    float s = 0.f;
    #pragma unroll 4
    for (int j = 0; j < EDIM; j++) s += row[j] * unk[j];
    d_induced[i] = s;
    for (int f = i; f < HDIM * BATCH; f += 256) d_h2[f] = 0.f;
}

// ---- gather: e2[t][b][:] = emb_table[tok] or induced ----
__global__ void gather_kernel(const int* __restrict__ x,
                              const float* __restrict__ emb) {
    int gid = blockIdx.x * 256 + threadIdx.x;          // one float4 each
    int row = gid >> 6;
    int q   = gid & 63;
    int t = row >> 5, b = row & 31;
    int tok = x[b * SEQ + t];
    float4 v;
    if (tok < 0) v = ((const float4*)d_induced)[q];
    else         v = *((const float4*)(emb + (size_t)tok * EDIM) + q);
    ((float4*)d_e2)[gid] = v;
}

// ---- xi GEMM (f32x2): xi[t][g][b] = sum_k e2[t][b][k]*W_ih[g][k] + b_ih[g] ----
__global__ void __launch_bounds__(256) xi_gemm_kernel(const float* __restrict__ W_ih,
                                                      const float* __restrict__ b_ih) {
    __shared__ __align__(16) float e_s[32 * 260];
    __shared__ __align__(16) float w_s[128 * 16];
    int t  = blockIdx.x;
    int g0 = blockIdx.y * 128;
    int tid = threadIdx.x;
    int w = tid >> 5, lane = tid & 31;

    const float* esrc = d_e2 + (size_t)t * BATCH * EDIM;
    for (int f = tid; f < 32 * 256; f += 256)
        e_s[(f >> 8) * 260 + (f & 255)] = esrc[f];

    unsigned long long acc[16];
    #pragma unroll
    for (int g = 0; g < 16; g++) acc[g] = 0ull;

    for (int kc = 0; kc < 256; kc += 16) {
        __syncthreads();
        for (int f = tid; f < 2048; f += 256)
            w_s[f] = W_ih[(size_t)(g0 + (f >> 4)) * EDIM + kc + (f & 15)];
        __syncthreads();
        const float* hrow = e_s + lane * 260 + kc;
        #pragma unroll
        for (int k4 = 0; k4 < 16; k4 += 4) {
            ulonglong2 hv = *(const ulonglong2*)(hrow + k4);
            #pragma unroll
            for (int g = 0; g < 16; g++) {
                ulonglong2 wv = *(const ulonglong2*)(w_s + (w * 16 + g) * 16 + k4);
                fma2(acc[g], hv.x, wv.x);
                fma2(acc[g], hv.y, wv.y);
            }
        }
    }
    float* orow = d_xi + ((size_t)t * G3 + g0 + w * 16) * BATCH + lane;
    #pragma unroll
    for (int g = 0; g < 16; g++) {
        float2 p = upk(acc[g]);
        orow[(size_t)g * BATCH] = p.x + p.y + b_ih[g0 + w * 16 + g];
    }
}

// ---- GRU recurrence v7: hierarchical atomic barrier ----
// CTA owns dims d0..d0+3 (12 W_hh rows in smem). warp w owns k in [32w,32w+32).
// lane = batch. h layout [buf][d][b] via .cg. Arrival: atomicAdd to 1-of-8 leaf
// counters (16 CTAs each, separate L2 lines); leaf-completer forwards to root;
// root-completer publishes d_gen. Cuts 128-way single-address serialization.
__global__ void __launch_bounds__(GRUT, 1)
gru_kernel(const float* __restrict__ W_hh, const float* __restrict__ b_hh) {
    extern __shared__ float sm[];
    float* w_s = sm;                        // [12][512]    (24576 B)
    float* red = sm + 12 * 512;             // [16][12][32] (24576 B)

    const int tid  = threadIdx.x;
    const int w    = tid >> 5, lane = tid & 31;

    for (int f = tid; f < 12 * 512; f += GRUT) {
        int r = f >> 9, k = f & 511;
        int gate = r >> 2, dd = r & 3;
        w_s[f] = W_hh[((size_t)gate * HDIM + blockIdx.x * DPC + dd) * HDIM + k];
    }
    float bh0 = 0.f, bh1 = 0.f, bh2 = 0.f;
    int d = 0;
    if (w < 4) {
        d = blockIdx.x * DPC + w;
        bh0 = b_hh[d]; bh1 = b_hh[HDIM + d]; bh2 = b_hh[2 * HDIM + d];
    }
    unsigned* myleaf = &d_leaf[(blockIdx.x & 7) * 32];
    float maxacc = -INFINITY;
    float hp = 0.f;                         // own h[d][lane], register-carried
    __syncthreads();

    for (int t = 0; t < SEQ; t++) {
        const float* hbuf = d_h2 + (t & 1) * HDIM * BATCH;

        // 0) prefetch xi[t] (finalize warps) — long-latency, hidden by dot
        float xr = 0.f, xz = 0.f, xn = 0.f;
        if (w < 4) {
            const float* xib = d_xi + (size_t)t * G3 * BATCH;
            xr = xib[(size_t)(0 * HDIM + d) * BATCH + lane];
            xz = xib[(size_t)(1 * HDIM + d) * BATCH + lane];
            xn = xib[(size_t)(2 * HDIM + d) * BATCH + lane];
        }

        // 1) load h chunk (32 coalesced .cg loads, MLP=32)
        float hk[32];
        const float* hc = hbuf + 32 * w * BATCH + lane;
        #pragma unroll
        for (int i = 0; i < 32; i++) hk[i] = ldcg(hc + i * BATCH);
        unsigned long long h2[16];
        #pragma unroll
        for (int i = 0; i < 16; i++) h2[i] = pk(hk[2 * i], hk[2 * i + 1]);

        // 2) all 12 rows x 32-K chunk via packed FFMA2 (192 instr/thread)
        unsigned long long acc[12];
        #pragma unroll
        for (int r = 0; r < 12; r++) acc[r] = 0ull;
        #pragma unroll
        for (int i = 0; i < 8; i++) {
            unsigned long long ha = h2[2 * i], hb = h2[2 * i + 1];
            #pragma unroll
            for (int r = 0; r < 12; r++) {
                ulonglong2 wv = *(const ulonglong2*)(w_s + r * 512 + 32 * w + 4 * i);
                fma2(acc[r], ha, wv.x);
                fma2(acc[r], hb, wv.y);
            }
        }
        #pragma unroll
        for (int r = 0; r < 12; r++) {
            float2 p = upk(acc[r]);
            red[(w * 12 + r) * 32 + lane] = p.x + p.y;
        }
        __syncthreads();

        // 3) finalize gates (warps 0..3; warp w = local dim, lane = batch)
        if (w < 4) {
            float sr = 0.f, sz = 0.f, sn = 0.f;
            #pragma unroll
            for (int kc = 0; kc < 16; kc++) {
                sr += red[(kc * 12 + 0 * 4 + w) * 32 + lane];
                sz += red[(kc * 12 + 1 * 4 + w) * 32 + lane];
                sn += red[(kc * 12 + 2 * 4 + w) * 32 + lane];
            }
            float rg = 1.f / (1.f + expf(-(xr + sr + bh0)));
            float zg = 1.f / (1.f + expf(-(xz + sz + bh1)));
            float ng = tanhf(xn + rg * (sn + bh2));      // torch: b_hh_n inside r*(.)
            float hnew = (1.f - zg) * ng + zg * hp;
            maxacc = fmaxf(maxacc, hnew);
            hp = hnew;
            stcg(d_h2 + ((t + 1) & 1) * HDIM * BATCH + d * BATCH + lane, hnew);
            __threadfence();                 // writers only: h visible pre-arrival
        }
        __syncthreads();                     // all writers fenced CTA-wide

        // 4) grid barrier: 2-level atomic tree + d_gen release
        if (t < SEQ - 1) {
            if (tid == 0) {
                unsigned step = (unsigned)(t + 1);
                unsigned a = atomicAdd(myleaf, 1u) + 1u;
                if (a == 16u * step) {                   // last of this leaf group
                    unsigned r = atomicAdd(&d_root, 1u) + 1u;
                    if (r == 8u * step) {                // last leaf overall
                        atomicExch(&d_gen, step);
                    } else {
                        while (*((volatile unsigned*)&d_gen) < step) { }
                    }
                } else {
                    while (*((volatile unsigned*)&d_gen) < step) { }
                }
            }
            __syncthreads();                 // release whole CTA
        }
    }
    if (w < 4) d_pooled[lane * HDIM + d] = maxacc;
}

// ---- projection: out[b][c] = pooled[b] . W_proj[c] + b_proj[c] ----
__global__ void proj_kernel(const float* __restrict__ Wp,
                            const float* __restrict__ bp,
                            float* __restrict__ out) {
    __shared__ float red[128];
    int b = blockIdx.x >> 1, c = blockIdx.x & 1;
    int tid = threadIdx.x;
    const float* pr = d_pooled + b * HDIM;
    const float* wr = Wp + c * HDIM;
    float s = 0.f;
    for (int k = tid; k < HDIM; k += 128) s += pr[k] * wr[k];
    red[tid] = s;
    __syncthreads();
    for (int off = 64; off > 0; off >>= 1) {
        if (tid < off) red[tid] += red[tid + off];
        __syncthreads();
    }
    if (tid == 0) out[b * 2 + c] = red[0] + bp[c];
}

extern "C" void kernel_launch(void* const* d_in, const int* in_sizes, int n_in,
                              void* d_out, int out_size) {
    const int*   x     = (const int*)  d_in[0];
    const float* emb   = (const float*)d_in[1];
    const float* unk   = (const float*)d_in[2];
    const float* induc = (const float*)d_in[3];
    const float* W_ih  = (const float*)d_in[4];
    const float* W_hh  = (const float*)d_in[5];
    const float* b_ih  = (const float*)d_in[6];
    const float* b_hh  = (const float*)d_in[7];
    const float* W_pr  = (const float*)d_in[8];
    const float* b_pr  = (const float*)d_in[9];
    float* out = (float*)d_out;

    size_t gru_smem = (12 * 512 + 16 * 12 * 32) * sizeof(float);  // 49152 B
    cudaFuncSetAttribute(gru_kernel, cudaFuncAttributeMaxDynamicSharedMemorySize,
                         (int)gru_smem);

    init_kernel<<<1, 256>>>(induc, unk);
    gather_kernel<<<(SEQ * BATCH * 64) / 256, 256>>>(x, emb);
    dim3 gg(SEQ, G3 / 128);
    xi_gemm_kernel<<<gg, 256>>>(W_ih, b_ih);
    gru_kernel<<<NCTA, GRUT, gru_smem>>>(W_hh, b_hh);
    proj_kernel<<<BATCH * 2, 128>>>(W_pr, b_pr, out);
}

// round 16
// speedup vs baseline: 1.1633x; 1.1633x over previous
#include <cuda_runtime.h>
#include <math.h>

#define EDIM   256
#define HDIM   512
#define BATCH  32
#define SEQ    512
#define G3     1536
#define NCTA   128
#define DPC    4
#define GRUT   512

// ---- f32x2 packed helpers (sm_103a FFMA2; full fp32 precision) ----
__device__ __forceinline__ void fma2(unsigned long long& a,
                                     unsigned long long x, unsigned long long y) {
    asm("fma.rn.f32x2 %0, %1, %2, %0;" : "+l"(a) : "l"(x), "l"(y));
}
__device__ __forceinline__ unsigned long long pk(float lo, float hi) {
    unsigned long long r;
    asm("mov.b64 %0, {%1, %2};" : "=l"(r) : "f"(lo), "f"(hi));
    return r;
}
__device__ __forceinline__ float2 upk(unsigned long long v) {
    float2 r; asm("mov.b64 {%0, %1}, %2;" : "=f"(r.x), "=f"(r.y) : "l"(v));
    return r;
}
__device__ __forceinline__ float ldcg(const float* p) {
    float v; asm volatile("ld.global.cg.f32 %0, [%1];" : "=f"(v) : "l"(p));
    return v;
}
__device__ __forceinline__ void stcg(float* p, float v) {
    asm volatile("st.global.cg.f32 [%0], %1;" :: "l"(p), "f"(v));
}
__device__ __forceinline__ float tanh_ap(float x) {
    float y; asm("tanh.approx.f32 %0, %1;" : "=f"(y) : "f"(x));
    return y;
}

// ---- scratch (device globals; no allocations allowed) ----
__device__ float d_induced[EDIM];
__device__ float d_e2[SEQ * BATCH * EDIM];            // [t][b][k]
__device__ float d_xi[(size_t)SEQ * G3 * BATCH];      // [t][g][b]
__device__ float d_h2[2 * HDIM * BATCH];              // [buf][d][b]
__device__ float d_pooled[BATCH * HDIM];              // [b][d]
__device__ unsigned d_cnt;                            // monotonic arrival counter
__device__ unsigned d_gen;                            // released generation

// ---- init: induced = induction @ unk, h0 = 0, barrier reset ----
__global__ void init_kernel(const float* __restrict__ induction,
                            const float* __restrict__ unk) {
    int i = threadIdx.x;                               // 256 threads
    if (i == 0) { d_cnt = 0u; d_gen = 0u; }
    const float* row = induction + (size_t)i * EDIM;
    float s = 0.f;
    #pragma unroll 4
    for (int j = 0; j < EDIM; j++) s += row[j] * unk[j];
    d_induced[i] = s;
    for (int f = i; f < HDIM * BATCH; f += 256) d_h2[f] = 0.f;
}

// ---- gather: e2[t][b][:] = emb_table[tok] or induced ----
__global__ void gather_kernel(const int* __restrict__ x,
                              const float* __restrict__ emb) {
    int gid = blockIdx.x * 256 + threadIdx.x;          // one float4 each
    int row = gid >> 6;
    int q   = gid & 63;
    int t = row >> 5, b = row & 31;
    int tok = x[b * SEQ + t];
    float4 v;
    if (tok < 0) v = ((const float4*)d_induced)[q];
    else         v = *((const float4*)(emb + (size_t)tok * EDIM) + q);
    ((float4*)d_e2)[gid] = v;
}

// ---- xi GEMM v2: full-tile staging, one sync, 2-timestep blocking ----
// grid (SEQ/2, 12), 512 threads. CTA: 2 timesteps (64 rows) x 128 gates, K=256.
// All weights (128x256) + both e tiles staged ONCE (197KB smem), single sync,
// then straight FFMA2. warp = 8 gates x 2 rows, lane = batch.
__global__ void __launch_bounds__(512) xi_gemm_kernel(const float* __restrict__ W_ih,
                                                      const float* __restrict__ b_ih) {
    extern __shared__ __align__(16) float xs[];
    float* w_s = xs;                       // [128][256]  (131072 B)
    float* e_s = xs + 128 * 256;           // [64][260]   ( 66560 B)
    int t0 = blockIdx.x * 2;
    int g0 = blockIdx.y * 128;
    int tid = threadIdx.x;
    int w = tid >> 5, lane = tid & 31;

    for (int f = tid; f < 128 * 256; f += 512)
        w_s[f] = W_ih[(size_t)(g0 + (f >> 8)) * EDIM + (f & 255)];
    const float* esrc = d_e2 + (size_t)t0 * BATCH * EDIM;
    for (int f = tid; f < 64 * 256; f += 512)
        e_s[(f >> 8) * 260 + (f & 255)] = esrc[f];
    __syncthreads();

    unsigned long long a0[8], a1[8];
    #pragma unroll
    for (int g = 0; g < 8; g++) { a0[g] = 0ull; a1[g] = 0ull; }

    const float* h0 = e_s + lane * 260;            // row lane   (t0)
    const float* h1 = e_s + (32 + lane) * 260;     // row 32+lane (t0+1)
    const float* wb = w_s + (w * 8) * 256;
    #pragma unroll 8
    for (int k4 = 0; k4 < 256; k4 += 4) {
        ulonglong2 hv0 = *(const ulonglong2*)(h0 + k4);
        ulonglong2 hv1 = *(const ulonglong2*)(h1 + k4);
        #pragma unroll
        for (int g = 0; g < 8; g++) {
            ulonglong2 wv = *(const ulonglong2*)(wb + g * 256 + k4);  // broadcast
            fma2(a0[g], hv0.x, wv.x);
            fma2(a0[g], hv0.y, wv.y);
            fma2(a1[g], hv1.x, wv.x);
            fma2(a1[g], hv1.y, wv.y);
        }
    }
    #pragma unroll
    for (int g = 0; g < 8; g++) {
        int gg = g0 + w * 8 + g;
        float bias = b_ih[gg];
        float2 p0 = upk(a0[g]);
        float2 p1 = upk(a1[g]);
        d_xi[((size_t)t0 * G3 + gg) * BATCH + lane]       = p0.x + p0.y + bias;
        d_xi[((size_t)(t0 + 1) * G3 + gg) * BATCH + lane] = p1.x + p1.y + bias;
    }
}

// ---- GRU recurrence v8: v6 skeleton (flat atomic barrier) + MUFU gates ----
// CTA owns dims d0..d0+3 (12 W_hh rows in smem). warp w owns k in [32w,32w+32).
// lane = batch. h layout [buf][d][b] via .cg. Writer-only fences; flat
// atomicAdd arrival + d_gen release (measured best: 2454us config).
__global__ void __launch_bounds__(GRUT, 1)
gru_kernel(const float* __restrict__ W_hh, const float* __restrict__ b_hh) {
    extern __shared__ float sm[];
    float* w_s = sm;                        // [12][512]    (24576 B)
    float* red = sm + 12 * 512;             // [16][12][32] (24576 B)

    const int tid  = threadIdx.x;
    const int w    = tid >> 5, lane = tid & 31;

    for (int f = tid; f < 12 * 512; f += GRUT) {
        int r = f >> 9, k = f & 511;
        int gate = r >> 2, dd = r & 3;
        w_s[f] = W_hh[((size_t)gate * HDIM + blockIdx.x * DPC + dd) * HDIM + k];
    }
    float bh0 = 0.f, bh1 = 0.f, bh2 = 0.f;
    int d = 0;
    if (w < 4) {
        d = blockIdx.x * DPC + w;
        bh0 = b_hh[d]; bh1 = b_hh[HDIM + d]; bh2 = b_hh[2 * HDIM + d];
    }
    float maxacc = -INFINITY;
    float hp = 0.f;                         // own h[d][lane], register-carried
    __syncthreads();

    for (int t = 0; t < SEQ; t++) {
        const float* hbuf = d_h2 + (t & 1) * HDIM * BATCH;

        // 0) prefetch xi[t] (finalize warps) — long-latency, hidden by dot
        float xr = 0.f, xz = 0.f, xn = 0.f;
        if (w < 4) {
            const float* xib = d_xi + (size_t)t * G3 * BATCH;
            xr = xib[(size_t)(0 * HDIM + d) * BATCH + lane];
            xz = xib[(size_t)(1 * HDIM + d) * BATCH + lane];
            xn = xib[(size_t)(2 * HDIM + d) * BATCH + lane];
        }

        // 1) load h chunk (32 coalesced .cg loads, MLP=32)
        float hk[32];
        const float* hc = hbuf + 32 * w * BATCH + lane;
        #pragma unroll
        for (int i = 0; i < 32; i++) hk[i] = ldcg(hc + i * BATCH);
        unsigned long long h2[16];
        #pragma unroll
        for (int i = 0; i < 16; i++) h2[i] = pk(hk[2 * i], hk[2 * i + 1]);

        // 2) all 12 rows x 32-K chunk via packed FFMA2 (192 instr/thread)
        unsigned long long acc[12];
        #pragma unroll
        for (int r = 0; r < 12; r++) acc[r] = 0ull;
        #pragma unroll
        for (int i = 0; i < 8; i++) {
            unsigned long long ha = h2[2 * i], hb = h2[2 * i + 1];
            #pragma unroll
            for (int r = 0; r < 12; r++) {
                ulonglong2 wv = *(const ulonglong2*)(w_s + r * 512 + 32 * w + 4 * i);
                fma2(acc[r], ha, wv.x);
                fma2(acc[r], hb, wv.y);
            }
        }
        #pragma unroll
        for (int r = 0; r < 12; r++) {
            float2 p = upk(acc[r]);
            red[(w * 12 + r) * 32 + lane] = p.x + p.y;
        }
        __syncthreads();

        // 3) finalize gates (warps 0..3; MUFU tanh.approx, sigmoid via tanh)
        if (w < 4) {
            float sr = 0.f, sz = 0.f, sn = 0.f;
            #pragma unroll
            for (int kc = 0; kc < 16; kc++) {
                sr += red[(kc * 12 + 0 * 4 + w) * 32 + lane];
                sz += red[(kc * 12 + 1 * 4 + w) * 32 + lane];
                sn += red[(kc * 12 + 2 * 4 + w) * 32 + lane];
            }
            float rg = 0.5f * tanh_ap(0.5f * (xr + sr + bh0)) + 0.5f;
            float zg = 0.5f * tanh_ap(0.5f * (xz + sz + bh1)) + 0.5f;
            float ng = tanh_ap(xn + rg * (sn + bh2));    // torch: b_hh_n inside r*(.)
            float hnew = (1.f - zg) * ng + zg * hp;
            maxacc = fmaxf(maxacc, hnew);
            hp = hnew;
            stcg(d_h2 + ((t + 1) & 1) * HDIM * BATCH + d * BATCH + lane, hnew);
            __threadfence();                 // writers only: h visible pre-arrival
        }
        __syncthreads();                     // all writers fenced CTA-wide

        // 4) grid barrier: flat atomicAdd arrival + d_gen release (proven)
        if (t < SEQ - 1) {
            if (tid == 0) {
                unsigned target = (unsigned)(t + 1) * NCTA;
                unsigned a = atomicAdd(&d_cnt, 1u) + 1u;
                if (a == target) {
                    atomicExch(&d_gen, (unsigned)(t + 1));
                } else {
                    while (*((volatile unsigned*)&d_gen) < (unsigned)(t + 1)) { }
                }
            }
            __syncthreads();                 // release whole CTA
        }
    }
    if (w < 4) d_pooled[lane * HDIM + d] = maxacc;
}

// ---- projection: out[b][c] = pooled[b] . W_proj[c] + b_proj[c] ----
__global__ void proj_kernel(const float* __restrict__ Wp,
                            const float* __restrict__ bp,
                            float* __restrict__ out) {
    __shared__ float red[128];
    int b = blockIdx.x >> 1, c = blockIdx.x & 1;
    int tid = threadIdx.x;
    const float* pr = d_pooled + b * HDIM;
    const float* wr = Wp + c * HDIM;
    float s = 0.f;
    for (int k = tid; k < HDIM; k += 128) s += pr[k] * wr[k];
    red[tid] = s;
    __syncthreads();
    for (int off = 64; off > 0; off >>= 1) {
        if (tid < off) red[tid] += red[tid + off];
        __syncthreads();
    }
    if (tid == 0) out[b * 2 + c] = red[0] + bp[c];
}

extern "C" void kernel_launch(void* const* d_in, const int* in_sizes, int n_in,
                              void* d_out, int out_size) {
    const int*   x     = (const int*)  d_in[0];
    const float* emb   = (const float*)d_in[1];
    const float* unk   = (const float*)d_in[2];
    const float* induc = (const float*)d_in[3];
    const float* W_ih  = (const float*)d_in[4];
    const float* W_hh  = (const float*)d_in[5];
    const float* b_ih  = (const float*)d_in[6];
    const float* b_hh  = (const float*)d_in[7];
    const float* W_pr  = (const float*)d_in[8];
    const float* b_pr  = (const float*)d_in[9];
    float* out = (float*)d_out;

    size_t xi_smem  = (128 * 256 + 64 * 260) * sizeof(float);     // 197632 B
    size_t gru_smem = (12 * 512 + 16 * 12 * 32) * sizeof(float);  //  49152 B
    cudaFuncSetAttribute(xi_gemm_kernel, cudaFuncAttributeMaxDynamicSharedMemorySize,
                         (int)xi_smem);
    cudaFuncSetAttribute(gru_kernel, cudaFuncAttributeMaxDynamicSharedMemorySize,
                         (int)gru_smem);

    init_kernel<<<1, 256>>>(induc, unk);
    gather_kernel<<<(SEQ * BATCH * 64) / 256, 256>>>(x, emb);
    dim3 gg(SEQ / 2, G3 / 128);
    xi_gemm_kernel<<<gg, 512, xi_smem>>>(W_ih, b_ih);
    gru_kernel<<<NCTA, GRUT, gru_smem>>>(W_hh, b_hh);
    proj_kernel<<<BATCH * 2, 128>>>(W_pr, b_pr, out);
}